// round 16
// baseline (speedup 1.0000x reference)
#include <cuda_runtime.h>
#include <cuda_fp16.h>
#include <cstdint>

#define D 1024
#define MAXR 16384
#define DD (D * D)
#define NRC 32                 // K chunks of 32
#define STAGE_B 32768          // A1 8K | A2 8K | B1 8K | B2 8K
#define NSTG 2
#define SMEM_SZ (NSTG * STAGE_B) // 64 KB -> 2 CTAs/SM
#define SRES 64.0f
#define NMB 128                // 128-row blocks over M=16384
#define TPS 1024               // tasks per stage
#define TOTAL_TASKS (7 * TPS)  // G0 + LN + G1..G5
#define GRID_P 296             // 2 CTAs x 148 SMs

// ---------------- device scratch (allocation-free rule) ----------------
__device__ __align__(256) __half g_a1[MAXR * D], g_a2[MAXR * D];
__device__ __align__(256) __half g_c1[MAXR * D], g_c2[MAXR * D];
__device__ __align__(256) float  g_q[MAXR * D];
__device__ __align__(256) __half g_w1[6 * DD], g_w2[6 * DD];
__device__ int g_done[6][NMB];
__device__ int g_next;

struct Cfg {
    const __half *A1, *A2, *B1, *B2;
    const float* bias;
    __half *C1, *C2;
    float* Cf;
    int act, wmode;
};
__device__ Cfg g_cfg[6];

// A-side scaled-residual pair: A1 = fp16(a), A2 = fp16(A1 + 64(a-A1))
__device__ __forceinline__ void splitp(float a, float b, uint32_t& p1, uint32_t& p2) {
    __half2 h1 = __floats2half2_rn(a, b);
    float2 f1 = __half22float2(h1);
    __half2 h2 = __floats2half2_rn(f1.x + SRES * (a - f1.x), f1.y + SRES * (b - f1.y));
    p1 = *reinterpret_cast<uint32_t*>(&h1);
    p2 = *reinterpret_cast<uint32_t*>(&h2);
}

// smem swizzle: row stride 64B, 4 x 16B chunks per row (conflict-free ldmatrix)
__device__ __forceinline__ uint32_t soff(int row, int c) {
    return (uint32_t)(row * 64 + ((c ^ ((row >> 1) & 3)) << 4));
}

#define LDSM4(r0, r1, r2, r3, addr)                                               \
    asm volatile("ldmatrix.sync.aligned.m8n8.x4.shared.b16 {%0,%1,%2,%3}, [%4];"  \
                 : "=r"(r0), "=r"(r1), "=r"(r2), "=r"(r3) : "r"(addr))

#define MMAF16(ac, af, bf)                                                        \
    asm volatile("mma.sync.aligned.m16n8k16.row.col.f32.f16.f16.f32 "             \
                 "{%0,%1,%2,%3}, {%4,%5,%6,%7}, {%8,%9}, {%0,%1,%2,%3};"          \
                 : "+f"((ac)[0]), "+f"((ac)[1]), "+f"((ac)[2]), "+f"((ac)[3])     \
                 : "r"((af)[0]), "r"((af)[1]), "r"((af)[2]), "r"((af)[3]),        \
                   "r"((bf)[0]), "r"((bf)[1]))

// ---------------- GEMM tile task (round-9 mainloop) ----------------
__device__ __forceinline__ void gemm_tile(const Cfg& c, int bm, int bn, uint32_t sb) {
    const int tid = threadIdx.x, lane = tid & 31, wid = tid >> 5;
    const int wm = (wid >> 2) * 64, wn = (wid & 3) * 32;

    float acc[4][4][4] = {};
    uint32_t a1f[4][4], a2f[4][4], b1f[4][2], b2f[4][2];

    auto stage_load = [&](int kt) {
        const uint32_t st = sb + (uint32_t)(kt & (NSTG - 1)) * STAGE_B;
        const int rk = kt * 32;
#pragma unroll
        for (int i = 0; i < 2; i++) {
            const int idx = tid + i * 256;
            const int row = idx >> 2, cc = idx & 3;
            const uint32_t off = soff(row, cc);
            const size_t ga = (size_t)(bm + row) * D + rk + cc * 8;
            const size_t gb = (size_t)(bn + row) * D + rk + cc * 8;
            asm volatile("cp.async.cg.shared.global [%0], [%1], 16;" :: "r"(st + off),         "l"(c.A1 + ga));
            asm volatile("cp.async.cg.shared.global [%0], [%1], 16;" :: "r"(st + 8192 + off),  "l"(c.A2 + ga));
            asm volatile("cp.async.cg.shared.global [%0], [%1], 16;" :: "r"(st + 16384 + off), "l"(c.B1 + gb));
            asm volatile("cp.async.cg.shared.global [%0], [%1], 16;" :: "r"(st + 24576 + off), "l"(c.B2 + gb));
        }
        asm volatile("cp.async.commit_group;" ::: "memory");
    };

    auto ld1 = [&](uint32_t st, int kk) {
        const int ar = wm + (lane & 15);
        const int ac_ = kk * 2 + (lane >> 4);
        const int br = wn + ((lane >> 4) << 3) + (lane & 7);
        const int bc = kk * 2 + ((lane >> 3) & 1);
#pragma unroll
        for (int mf = 0; mf < 4; mf++)
            LDSM4(a1f[mf][0], a1f[mf][1], a1f[mf][2], a1f[mf][3],
                  st + soff(ar + mf * 16, ac_));
#pragma unroll
        for (int g = 0; g < 2; g++) {
            uint32_t r0, r1, r2, r3;
            LDSM4(r0, r1, r2, r3, st + 16384 + soff(br + g * 16, bc));
            b1f[g * 2][0] = r0; b1f[g * 2][1] = r1;
            b1f[g * 2 + 1][0] = r2; b1f[g * 2 + 1][1] = r3;
        }
    };
    auto ld2 = [&](uint32_t st, int kk) {
        const int ar = wm + (lane & 15);
        const int ac_ = kk * 2 + (lane >> 4);
        const int br = wn + ((lane >> 4) << 3) + (lane & 7);
        const int bc = kk * 2 + ((lane >> 3) & 1);
#pragma unroll
        for (int mf = 0; mf < 4; mf++)
            LDSM4(a2f[mf][0], a2f[mf][1], a2f[mf][2], a2f[mf][3],
                  st + 8192 + soff(ar + mf * 16, ac_));
#pragma unroll
        for (int g = 0; g < 2; g++) {
            uint32_t r0, r1, r2, r3;
            LDSM4(r0, r1, r2, r3, st + 24576 + soff(br + g * 16, bc));
            b2f[g * 2][0] = r0; b2f[g * 2][1] = r1;
            b2f[g * 2 + 1][0] = r2; b2f[g * 2 + 1][1] = r3;
        }
    };

    auto mma1 = [&]() {
#pragma unroll
        for (int mf = 0; mf < 4; mf++)
#pragma unroll
            for (int nf = 0; nf < 4; nf++)
                MMAF16(acc[mf][nf], a1f[mf], b1f[nf]);
    };
    auto mma2 = [&]() {
#pragma unroll
        for (int mf = 0; mf < 4; mf++)
#pragma unroll
            for (int nf = 0; nf < 4; nf++)
                MMAF16(acc[mf][nf], a2f[mf], b2f[nf]);
    };

    stage_load(0);
    asm volatile("cp.async.wait_group 0;" ::: "memory");
    __syncthreads();
    ld1(sb, 0);

    for (int kt = 0; kt < NRC; kt++) {
        const uint32_t st = sb + (uint32_t)(kt & (NSTG - 1)) * STAGE_B;
        ld2(st, 0);
        if (kt + 1 < NRC) stage_load(kt + 1);
        mma1();
        ld1(st, 1);
        mma2();
        ld2(st, 1);
        mma1();
        if (kt + 1 < NRC) {
            asm volatile("cp.async.wait_group 0;" ::: "memory");
            __syncthreads();
            ld1(sb + (uint32_t)((kt + 1) & (NSTG - 1)) * STAGE_B, 0);
        }
        mma2();
    }

    float2 bias2[4];
#pragma unroll
    for (int nf = 0; nf < 4; nf++)
        bias2[nf] = __ldg((const float2*)(c.bias + bn + wn + nf * 8 + (lane & 3) * 2));

#pragma unroll
    for (int mf = 0; mf < 4; mf++) {
#pragma unroll
        for (int rh = 0; rh < 2; rh++) {
            const int row = bm + wm + mf * 16 + (lane >> 2) + rh * 8;
#pragma unroll
            for (int nf = 0; nf < 4; nf++) {
                const int n = bn + wn + nf * 8 + (lane & 3) * 2;
                float v0 = acc[mf][nf][rh * 2 + 0] + bias2[nf].x;
                float v1 = acc[mf][nf][rh * 2 + 1] + bias2[nf].y;
                if (c.act) {
                    v0 = v0 / (1.0f + __expf(-v0));
                    v1 = v1 / (1.0f + __expf(-v1));
                }
                if (c.wmode == 0) {
                    uint32_t q1, q2;
                    splitp(v0, v1, q1, q2);
                    *(uint32_t*)(c.C1 + (size_t)row * D + n) = q1;
                    *(uint32_t*)(c.C2 + (size_t)row * D + n) = q2;
                } else {
                    *(float2*)(c.Cf + (size_t)row * D + n) = make_float2(v0, v1);
                }
            }
        }
    }
}

// ---------------- dependency helpers ----------------
__device__ __forceinline__ void wait_block(int stage, int mi) {
    if (threadIdx.x == 0) {
        volatile int* p = &g_done[stage][mi];
        while (*p < 8) { }
        __threadfence();
    }
    __syncthreads();
}
__device__ __forceinline__ void publish(int stage, int mi) {
    __syncthreads();
    if (threadIdx.x == 0) {
        __threadfence();
        atomicAdd(&g_done[stage][mi], 1);
    }
}

// ---------------- persistent megakernel ----------------
__global__ void __launch_bounds__(256, 2) mega() {
    extern __shared__ __align__(128) char smem[];
    const uint32_t sb = (uint32_t)__cvta_generic_to_shared(smem);
    const int tid = threadIdx.x;
    __shared__ int s_task;

    for (;;) {
        if (tid == 0) s_task = atomicAdd(&g_next, 1);
        __syncthreads();
        const int t = s_task;
        if (t >= TOTAL_TASKS) break;

        if (t >= TPS && t < 2 * TPS) {
            // LayerNorm: warp-per-row, each lane covers 8 float4 (full 1024 row)
            const int i = t - TPS;
            wait_block(0, i >> 3);
            const int lane = tid & 31, w = tid >> 5;
#pragma unroll
            for (int rr = 0; rr < 2; rr++) {
                const int row = i * 16 + w * 2 + rr;
                const float4* src = (const float4*)(g_q + (size_t)row * D);
                float4 v[8];
                float s = 0.0f, ss = 0.0f;
#pragma unroll
                for (int k = 0; k < 8; k++) {
                    v[k] = __ldcg(src + lane + 32 * k);
                    s  += v[k].x + v[k].y + v[k].z + v[k].w;
                    ss += v[k].x * v[k].x + v[k].y * v[k].y +
                          v[k].z * v[k].z + v[k].w * v[k].w;
                }
#pragma unroll
                for (int o = 16; o > 0; o >>= 1) {
                    s  += __shfl_xor_sync(0xFFFFFFFFu, s,  o);
                    ss += __shfl_xor_sync(0xFFFFFFFFu, ss, o);
                }
                const float mu = s * (1.0f / D);
                const float var = ss * (1.0f / D) - mu * mu;
                const float r = rsqrtf(var + 1e-5f);
                uint32_t* d1 = (uint32_t*)g_c1 + (size_t)row * (D / 2);
                uint32_t* d2 = (uint32_t*)g_c2 + (size_t)row * (D / 2);
#pragma unroll
                for (int k = 0; k < 8; k++) {
                    uint2 h, l;
                    splitp((v[k].x - mu) * r, (v[k].y - mu) * r, h.x, l.x);
                    splitp((v[k].z - mu) * r, (v[k].w - mu) * r, h.y, l.y);
                    *(uint2*)(d1 + (lane + 32 * k) * 2) = h;
                    *(uint2*)(d2 + (lane + 32 * k) * 2) = l;
                }
            }
            publish(1, i >> 3);
        } else {
            const int gi = (t < TPS) ? 0 : 1 + (t - 2 * TPS) / TPS;
            const int r = (t < TPS) ? t : (t - 2 * TPS) % TPS;
            const int mi = r >> 3, ni = r & 7;
            if (gi > 0) wait_block(gi, mi);
            gemm_tile(g_cfg[gi], mi * 128, ni * 128, sb);
            if (gi == 0) publish(0, mi);
            else if (gi < 5) publish(gi + 1, mi);
        }
        __syncthreads();
    }
}

// ---------------- prep kernels ----------------
__global__ void __launch_bounds__(256)
reset_and_cfg(const float* bq, const float* mlp_b, const float* b_out, float* out) {
    const int i = blockIdx.x * 256 + threadIdx.x;
    if (i < 6 * NMB) ((int*)g_done)[i] = 0;
    if (i == 0) {
        g_next = 0;
        g_cfg[0] = {g_a1, g_a2, g_w1,           g_w2,           bq,          nullptr, nullptr, g_q,     0, 1};
        g_cfg[1] = {g_c1, g_c2, g_w1 + 1ull*DD, g_w2 + 1ull*DD, mlp_b,       g_a1,    g_a2,    nullptr, 1, 0};
        g_cfg[2] = {g_a1, g_a2, g_w1 + 2ull*DD, g_w2 + 2ull*DD, mlp_b + D,   g_c1,    g_c2,    nullptr, 1, 0};
        g_cfg[3] = {g_c1, g_c2, g_w1 + 3ull*DD, g_w2 + 3ull*DD, mlp_b + 2*D, g_a1,    g_a2,    nullptr, 1, 0};
        g_cfg[4] = {g_a1, g_a2, g_w1 + 4ull*DD, g_w2 + 4ull*DD, mlp_b + 3*D, g_c1,    g_c2,    nullptr, 0, 0};
        g_cfg[5] = {g_c1, g_c2, g_w1 + 5ull*DD, g_w2 + 5ull*DD, b_out,       nullptr, nullptr, out,     0, 1};
    }
}

__global__ void __launch_bounds__(256) xsplit(const float2* __restrict__ x,
                                              uint32_t* __restrict__ p1,
                                              uint32_t* __restrict__ p2) {
    size_t i = (size_t)blockIdx.x * 256 + threadIdx.x;
    float2 v = x[i];
    uint32_t a, b;
    splitp(v.x, v.y, a, b);
    p1[i] = a; p2[i] = b;
}

// all 6 weights: W[k][n] -> T[n][k], B-side scaled planes:
// B1s = fp16(63b/64), e1 = 63b/64 - B1s, B2s = fp16(b/64 + e1)
__global__ void __launch_bounds__(256)
wsplit_all(const float* __restrict__ wq, const float* __restrict__ mlp_w,
           const float* __restrict__ w_out,
           __half* __restrict__ T1, __half* __restrict__ T2) {
    __shared__ float t[32][33];
    const int z = blockIdx.z;
    const float* W = (z == 0) ? wq : (z <= 4 ? mlp_w + (size_t)(z - 1) * DD : w_out);
    __half* t1 = T1 + (size_t)z * DD;
    __half* t2 = T2 + (size_t)z * DD;
    const int bx = blockIdx.x * 32, by = blockIdx.y * 32;
    const int tx = threadIdx.x, ty = threadIdx.y;
#pragma unroll
    for (int i = 0; i < 32; i += 8) t[ty + i][tx] = W[(size_t)(by + ty + i) * D + bx + tx];
    __syncthreads();
#pragma unroll
    for (int i = 0; i < 32; i += 8) {
        float b = t[tx][ty + i];
        float bmain = b * (63.0f / 64.0f);
        __half h1 = __float2half_rn(bmain);
        float e1 = bmain - __half2float(h1);
        __half h2 = __float2half_rn(b * (1.0f / 64.0f) + e1);
        size_t o = (size_t)(bx + ty + i) * D + by + tx;
        t1[o] = h1;
        t2[o] = h2;
    }
}

// ---------------- launch ----------------
extern "C" void kernel_launch(void* const* d_in, const int* in_sizes, int n_in,
                              void* d_out, int out_size) {
    const float* x     = (const float*)d_in[0];
    const float* wq    = (const float*)d_in[1];
    const float* bq    = (const float*)d_in[2];
    const float* mlp_w = (const float*)d_in[3];
    const float* mlp_b = (const float*)d_in[4];
    const float* w_out = (const float*)d_in[5];
    const float* b_out = (const float*)d_in[6];
    float* out = (float*)d_out;
    const int M = in_sizes[0] / D;   // 16384

    __half *a1, *a2, *w1, *w2;
    cudaGetSymbolAddress((void**)&a1, g_a1);
    cudaGetSymbolAddress((void**)&a2, g_a2);
    cudaGetSymbolAddress((void**)&w1, g_w1);
    cudaGetSymbolAddress((void**)&w2, g_w2);

    cudaFuncSetAttribute(mega, cudaFuncAttributeMaxDynamicSharedMemorySize, SMEM_SZ);

    dim3 wg(D / 32, D / 32, 6), wb(32, 8);
    wsplit_all<<<wg, wb>>>(wq, mlp_w, w_out, w1, w2);
    xsplit<<<(M * D) / 512, 256>>>((const float2*)x, (uint32_t*)a1, (uint32_t*)a2);
    reset_and_cfg<<<3, 256>>>(bq, mlp_b, b_out, out);

    mega<<<GRID_P, 256, SMEM_SZ>>>();
}

// round 17
// speedup vs baseline: 1.2994x; 1.2994x over previous
#include <cuda_runtime.h>
#include <cuda_fp16.h>
#include <cstdint>

#define D 1024
#define MAXR 16384
#define DD (D * D)
#define NRC 32                 // K chunks of 32
#define STAGE 32768            // A1 8K | A2 8K | B1 8K | B2 8K
#define NSTG 2
#define SMEM_SZ (NSTG * STAGE) // 64 KB -> 2 CTAs/SM
#define SRES 64.0f
#define NTH 128                // 4 warps

// ---------------- device scratch (allocation-free rule) ----------------
__device__ __align__(256) __half g_a1[MAXR * D], g_a2[MAXR * D];
__device__ __align__(256) __half g_c1[MAXR * D], g_c2[MAXR * D];
__device__ __align__(256) float  g_q[MAXR * D];
__device__ __align__(256) __half g_w1[6 * DD], g_w2[6 * DD];

// A-side scaled-residual pair: A1 = fp16(a), A2 = fp16(A1 + 64(a-A1))
__device__ __forceinline__ void splitp(float a, float b, uint32_t& p1, uint32_t& p2) {
    __half2 h1 = __floats2half2_rn(a, b);
    float2 f1 = __half22float2(h1);
    __half2 h2 = __floats2half2_rn(f1.x + SRES * (a - f1.x), f1.y + SRES * (b - f1.y));
    p1 = *reinterpret_cast<uint32_t*>(&h1);
    p2 = *reinterpret_cast<uint32_t*>(&h2);
}

// smem swizzle: row stride 64B, 4 x 16B chunks per row (conflict-free ldmatrix)
__device__ __forceinline__ uint32_t soff(int row, int c) {
    return (uint32_t)(row * 64 + ((c ^ ((row >> 1) & 3)) << 4));
}

#define LDSM4(r0, r1, r2, r3, addr)                                               \
    asm volatile("ldmatrix.sync.aligned.m8n8.x4.shared.b16 {%0,%1,%2,%3}, [%4];"  \
                 : "=r"(r0), "=r"(r1), "=r"(r2), "=r"(r3) : "r"(addr))

#define MMAF16(ac, af, bf)                                                        \
    asm volatile("mma.sync.aligned.m16n8k16.row.col.f32.f16.f16.f32 "             \
                 "{%0,%1,%2,%3}, {%4,%5,%6,%7}, {%8,%9}, {%0,%1,%2,%3};"          \
                 : "+f"((ac)[0]), "+f"((ac)[1]), "+f"((ac)[2]), "+f"((ac)[3])     \
                 : "r"((af)[0]), "r"((af)[1]), "r"((af)[2]), "r"((af)[3]),        \
                   "r"((bf)[0]), "r"((bf)[1]))

// ---------------- HMMA single-accumulator 2-plane GEMM ----------------
// 4 warps, 2x2 layout, warp tile 64x64. CTA tile 128x128.
// C = Sum A1*B1s + Sum A2*B2s + bias ; ACT 1 = silu.
// WMODE: 0 = write fp16 plane pair, 1 = write fp32.
template <int ACT, int WMODE>
__global__ void __launch_bounds__(NTH, 2)
gemm_hmma(const __half* __restrict__ A1, const __half* __restrict__ A2,
          const __half* __restrict__ B1, const __half* __restrict__ B2,
          const float* __restrict__ bias,
          __half* __restrict__ C1, __half* __restrict__ C2,
          float* __restrict__ Cf) {
    extern __shared__ __align__(128) char smem[];
    const int tid = threadIdx.x, lane = tid & 31, wid = tid >> 5;
    const int bm = blockIdx.y * 128, bn = blockIdx.x * 128;
    const int wm = (wid >> 1) * 64, wn = (wid & 1) * 64;
    const uint32_t sb = (uint32_t)__cvta_generic_to_shared(smem);

    float acc[4][8][4] = {};
    uint32_t a1f[4][4], a2f[4][4], b1f[8][2], b2f[8][2];

    auto stage_load = [&](int kt) {
        const uint32_t st = sb + (uint32_t)(kt & (NSTG - 1)) * STAGE;
        const int rk = kt * 32;
#pragma unroll
        for (int i = 0; i < 4; i++) {
            const int idx = tid + i * NTH;
            const int row = idx >> 2, c = idx & 3;
            const uint32_t off = soff(row, c);
            const size_t ga = (size_t)(bm + row) * D + rk + c * 8;
            const size_t gb = (size_t)(bn + row) * D + rk + c * 8;
            asm volatile("cp.async.cg.shared.global [%0], [%1], 16;" :: "r"(st + off),         "l"(A1 + ga));
            asm volatile("cp.async.cg.shared.global [%0], [%1], 16;" :: "r"(st + 8192 + off),  "l"(A2 + ga));
            asm volatile("cp.async.cg.shared.global [%0], [%1], 16;" :: "r"(st + 16384 + off), "l"(B1 + gb));
            asm volatile("cp.async.cg.shared.global [%0], [%1], 16;" :: "r"(st + 24576 + off), "l"(B2 + gb));
        }
        asm volatile("cp.async.commit_group;" ::: "memory");
    };

    auto ld1 = [&](uint32_t st, int kk) {   // A1 + B1s fragments
        const int ar = wm + (lane & 15);
        const int ac_ = kk * 2 + (lane >> 4);
        const int br = wn + ((lane >> 4) << 3) + (lane & 7);
        const int bc = kk * 2 + ((lane >> 3) & 1);
#pragma unroll
        for (int mf = 0; mf < 4; mf++)
            LDSM4(a1f[mf][0], a1f[mf][1], a1f[mf][2], a1f[mf][3],
                  st + soff(ar + mf * 16, ac_));
#pragma unroll
        for (int g = 0; g < 4; g++) {
            uint32_t r0, r1, r2, r3;
            LDSM4(r0, r1, r2, r3, st + 16384 + soff(br + g * 16, bc));
            b1f[g * 2][0] = r0; b1f[g * 2][1] = r1;
            b1f[g * 2 + 1][0] = r2; b1f[g * 2 + 1][1] = r3;
        }
    };
    auto ld2 = [&](uint32_t st, int kk) {   // A2 + B2s fragments
        const int ar = wm + (lane & 15);
        const int ac_ = kk * 2 + (lane >> 4);
        const int br = wn + ((lane >> 4) << 3) + (lane & 7);
        const int bc = kk * 2 + ((lane >> 3) & 1);
#pragma unroll
        for (int mf = 0; mf < 4; mf++)
            LDSM4(a2f[mf][0], a2f[mf][1], a2f[mf][2], a2f[mf][3],
                  st + 8192 + soff(ar + mf * 16, ac_));
#pragma unroll
        for (int g = 0; g < 4; g++) {
            uint32_t r0, r1, r2, r3;
            LDSM4(r0, r1, r2, r3, st + 24576 + soff(br + g * 16, bc));
            b2f[g * 2][0] = r0; b2f[g * 2][1] = r1;
            b2f[g * 2 + 1][0] = r2; b2f[g * 2 + 1][1] = r3;
        }
    };

    auto mma1 = [&]() {
#pragma unroll
        for (int mf = 0; mf < 4; mf++)
#pragma unroll
            for (int nf = 0; nf < 8; nf++)
                MMAF16(acc[mf][nf], a1f[mf], b1f[nf]);
    };
    auto mma2 = [&]() {
#pragma unroll
        for (int mf = 0; mf < 4; mf++)
#pragma unroll
            for (int nf = 0; nf < 8; nf++)
                MMAF16(acc[mf][nf], a2f[mf], b2f[nf]);
    };

    stage_load(0);
    asm volatile("cp.async.wait_group 0;" ::: "memory");
    __syncthreads();
    ld1(sb, 0);

    for (int kt = 0; kt < NRC; kt++) {
        const uint32_t st = sb + (uint32_t)(kt & (NSTG - 1)) * STAGE;
        ld2(st, 0);
        if (kt + 1 < NRC) stage_load(kt + 1);
        mma1();                        // P1 kh0 (hides ld2 kh0 + stage_load)
        ld1(st, 1);
        mma2();                        // P2 kh0 (hides ld1 kh1)
        ld2(st, 1);
        mma1();                        // P1 kh1 (hides ld2 kh1)
        if (kt + 1 < NRC) {
            asm volatile("cp.async.wait_group 0;" ::: "memory");
            __syncthreads();
            ld1(sb + (uint32_t)((kt + 1) & (NSTG - 1)) * STAGE, 0);
        }
        mma2();                        // P2 kh1 (hides next-chunk ld1)
    }

    // ---- epilogue: bias (+silu), store ----
    float2 bias2[8];
#pragma unroll
    for (int nf = 0; nf < 8; nf++)
        bias2[nf] = __ldg((const float2*)(bias + bn + wn + nf * 8 + (lane & 3) * 2));

#pragma unroll
    for (int mf = 0; mf < 4; mf++) {
#pragma unroll
        for (int rh = 0; rh < 2; rh++) {
            const int row = bm + wm + mf * 16 + (lane >> 2) + rh * 8;
#pragma unroll
            for (int nf = 0; nf < 8; nf++) {
                const int n = bn + wn + nf * 8 + (lane & 3) * 2;
                float v0 = acc[mf][nf][rh * 2 + 0] + bias2[nf].x;
                float v1 = acc[mf][nf][rh * 2 + 1] + bias2[nf].y;
                if (ACT == 1) {
                    v0 = v0 / (1.0f + __expf(-v0));
                    v1 = v1 / (1.0f + __expf(-v1));
                }
                if (WMODE == 0) {
                    uint32_t q1, q2;
                    splitp(v0, v1, q1, q2);
                    *(uint32_t*)(C1 + (size_t)row * D + n) = q1;
                    *(uint32_t*)(C2 + (size_t)row * D + n) = q2;
                } else {
                    *(float2*)(Cf + (size_t)row * D + n) = make_float2(v0, v1);
                }
            }
        }
    }
}

// ---------------- aux kernels ----------------
__global__ void __launch_bounds__(256) xsplit(const float2* __restrict__ x,
                                              uint32_t* __restrict__ p1,
                                              uint32_t* __restrict__ p2) {
    size_t i = (size_t)blockIdx.x * 256 + threadIdx.x;
    float2 v = x[i];
    uint32_t a, b;
    splitp(v.x, v.y, a, b);
    p1[i] = a; p2[i] = b;
}

// all 6 weights: W[k][n] -> T[n][k], B-side scaled planes:
// B1s = fp16(63b/64), e1 = 63b/64 - B1s, B2s = fp16(b/64 + e1)
__global__ void __launch_bounds__(256)
wsplit_all(const float* __restrict__ wq, const float* __restrict__ mlp_w,
           const float* __restrict__ w_out,
           __half* __restrict__ T1, __half* __restrict__ T2) {
    __shared__ float t[32][33];
    const int z = blockIdx.z;
    const float* W = (z == 0) ? wq : (z <= 4 ? mlp_w + (size_t)(z - 1) * DD : w_out);
    __half* t1 = T1 + (size_t)z * DD;
    __half* t2 = T2 + (size_t)z * DD;
    const int bx = blockIdx.x * 32, by = blockIdx.y * 32;
    const int tx = threadIdx.x, ty = threadIdx.y;
#pragma unroll
    for (int i = 0; i < 32; i += 8) t[ty + i][tx] = W[(size_t)(by + ty + i) * D + bx + tx];
    __syncthreads();
#pragma unroll
    for (int i = 0; i < 32; i += 8) {
        float b = t[tx][ty + i];
        float bmain = b * (63.0f / 64.0f);
        __half h1 = __float2half_rn(bmain);
        float e1 = bmain - __half2float(h1);
        __half h2 = __float2half_rn(b * (1.0f / 64.0f) + e1);
        size_t o = (size_t)(bx + ty + i) * D + by + tx;
        t1[o] = h1;
        t2[o] = h2;
    }
}

// LayerNorm (D=1024, eps=1e-5, no affine) fused with plane-pair output
__global__ void __launch_bounds__(256) ln_split(const float* __restrict__ in,
                                                uint32_t* __restrict__ p1,
                                                uint32_t* __restrict__ p2) {
    __shared__ float2 red[8];
    const int row = blockIdx.x;
    const int tid = threadIdx.x;
    const float4 v = *(const float4*)(in + (size_t)row * D + tid * 4);
    float s = v.x + v.y + v.z + v.w;
    float ss = v.x * v.x + v.y * v.y + v.z * v.z + v.w * v.w;
#pragma unroll
    for (int o = 16; o > 0; o >>= 1) {
        s += __shfl_xor_sync(0xFFFFFFFFu, s, o);
        ss += __shfl_xor_sync(0xFFFFFFFFu, ss, o);
    }
    if ((tid & 31) == 0) red[tid >> 5] = make_float2(s, ss);
    __syncthreads();
    if (tid < 32) {
        float2 r0 = (tid < 8) ? red[tid] : make_float2(0.f, 0.f);
        s = r0.x; ss = r0.y;
#pragma unroll
        for (int o = 4; o > 0; o >>= 1) {
            s += __shfl_xor_sync(0xFFFFFFFFu, s, o);
            ss += __shfl_xor_sync(0xFFFFFFFFu, ss, o);
        }
        if (tid == 0) red[0] = make_float2(s, ss);
    }
    __syncthreads();
    const float mu = red[0].x * (1.0f / D);
    const float var = red[0].y * (1.0f / D) - mu * mu;
    const float r = rsqrtf(var + 1e-5f);
    uint2 h1, h2;
    splitp((v.x - mu) * r, (v.y - mu) * r, h1.x, h2.x);
    splitp((v.z - mu) * r, (v.w - mu) * r, h1.y, h2.y);
    *(uint2*)&p1[(size_t)row * (D / 2) + tid * 2] = h1;
    *(uint2*)&p2[(size_t)row * (D / 2) + tid * 2] = h2;
}

// ---------------- launch ----------------
extern "C" void kernel_launch(void* const* d_in, const int* in_sizes, int n_in,
                              void* d_out, int out_size) {
    const float* x     = (const float*)d_in[0];
    const float* wq    = (const float*)d_in[1];
    const float* bq    = (const float*)d_in[2];
    const float* mlp_w = (const float*)d_in[3];
    const float* mlp_b = (const float*)d_in[4];
    const float* w_out = (const float*)d_in[5];
    const float* b_out = (const float*)d_in[6];
    float* out = (float*)d_out;
    const int M = in_sizes[0] / D;   // 16384

    __half *a1, *a2, *c1, *c2, *w1, *w2;
    float* q;
    cudaGetSymbolAddress((void**)&a1, g_a1);
    cudaGetSymbolAddress((void**)&a2, g_a2);
    cudaGetSymbolAddress((void**)&c1, g_c1);
    cudaGetSymbolAddress((void**)&c2, g_c2);
    cudaGetSymbolAddress((void**)&w1, g_w1);
    cudaGetSymbolAddress((void**)&w2, g_w2);
    cudaGetSymbolAddress((void**)&q, g_q);

    cudaFuncSetAttribute(gemm_hmma<0, 1>, cudaFuncAttributeMaxDynamicSharedMemorySize, SMEM_SZ);
    cudaFuncSetAttribute(gemm_hmma<1, 0>, cudaFuncAttributeMaxDynamicSharedMemorySize, SMEM_SZ);
    cudaFuncSetAttribute(gemm_hmma<0, 0>, cudaFuncAttributeMaxDynamicSharedMemorySize, SMEM_SZ);

    dim3 wg(D / 32, D / 32, 6), wb(32, 8);
    wsplit_all<<<wg, wb>>>(wq, mlp_w, w_out, w1, w2);

    xsplit<<<(M * D) / 512, 256>>>((const float2*)x, (uint32_t*)a1, (uint32_t*)a2);

    dim3 gg(D / 128, M / 128), bb(NTH);
    // q = x @ wq + bq (fp32 out)
    gemm_hmma<0, 1><<<gg, bb, SMEM_SZ>>>(a1, a2, w1, w2, bq, nullptr, nullptr, q);
    // q_norm = LN(q) -> plane pair
    ln_split<<<M, 256>>>(q, (uint32_t*)c1, (uint32_t*)c2);
    // memory MLP: 3x (GEMM+SiLU), final GEMM no act
    gemm_hmma<1, 0><<<gg, bb, SMEM_SZ>>>(c1, c2, w1 + 1ull * DD, w2 + 1ull * DD, mlp_b + 0 * D, a1, a2, nullptr);
    gemm_hmma<1, 0><<<gg, bb, SMEM_SZ>>>(a1, a2, w1 + 2ull * DD, w2 + 2ull * DD, mlp_b + 1 * D, c1, c2, nullptr);
    gemm_hmma<1, 0><<<gg, bb, SMEM_SZ>>>(c1, c2, w1 + 3ull * DD, w2 + 3ull * DD, mlp_b + 2 * D, a1, a2, nullptr);
    gemm_hmma<0, 0><<<gg, bb, SMEM_SZ>>>(a1, a2, w1 + 4ull * DD, w2 + 4ull * DD, mlp_b + 3 * D, c1, c2, nullptr);
    // out = h @ w_out + b_out (straight-through term is 0 in forward)
    gemm_hmma<0, 1><<<gg, bb, SMEM_SZ>>>(c1, c2, w1 + 5ull * DD, w2 + 5ull * DD, b_out, nullptr, nullptr, out);
}